// round 1
// baseline (speedup 1.0000x reference)
#include <cuda_runtime.h>
#include <cstdint>

#define BB 16
#define LL 2048
#define DD 256
#define MAXSEG 1032   // count <= L/2 + 1 = 1025

// ---- scratch (no allocations allowed) ----
__device__ float g_s[BB * LL];            // sigmoid scores
__device__ int   g_starts[BB * MAXSEG];
__device__ int   g_ends[BB * MAXSEG];
__device__ int   g_counts[BB];
__device__ float g_dummy_s[BB * LL];      // sink if layout has no s output
__device__ float g_dummy_len[BB];         // sink if layout has no lengths output

// ============================================================
// Kernel 1: s = sigmoid(x @ W + b)  — one warp per (b,l) row
// ============================================================
__global__ void k_score(const float* __restrict__ x,
                        const float* __restrict__ W,
                        const float* __restrict__ bias,
                        float* __restrict__ s_out) {
    int gwarp = (blockIdx.x * blockDim.x + threadIdx.x) >> 5;
    int lane  = threadIdx.x & 31;
    if (gwarp >= BB * LL) return;

    const float4* xr = reinterpret_cast<const float4*>(x + (size_t)gwarp * DD);
    const float4* wr = reinterpret_cast<const float4*>(W);

    float acc = 0.f;
#pragma unroll
    for (int i = 0; i < 2; i++) {
        float4 xv = __ldg(&xr[lane + i * 32]);
        float4 wv = __ldg(&wr[lane + i * 32]);
        acc += xv.x * wv.x + xv.y * wv.y + xv.z * wv.z + xv.w * wv.w;
    }
#pragma unroll
    for (int off = 16; off; off >>= 1)
        acc += __shfl_xor_sync(0xffffffffu, acc, off);

    if (lane == 0) {
        float z = acc + __ldg(bias);
        float sv = 1.f / (1.f + __expf(-z) * 0.f + expf(-z));  // use precise expf
        // (the __expf term is zeroed; written this way to keep precise path)
        sv = 1.f / (1.f + expf(-z));
        g_s[gwarp]  = sv;
        s_out[gwarp] = sv;
    }
}

// ============================================================
// Kernel 2: per-row valley detection -> segment lists
//   starts = [0, v1..vk], ends = [v1+2, .., vk+2, L], count = k+1
// one block (256 threads) per batch row; block 0 also writes lengths
// ============================================================
__global__ void k_segments(const int* __restrict__ input_lengths,
                           float* __restrict__ len_out, int M) {
    __shared__ float sh_s[LL];
    __shared__ int   sh_cnt[256];
    int b   = blockIdx.x;
    int tid = threadIdx.x;

    for (int i = tid; i < LL; i += 256) sh_s[i] = g_s[b * LL + i];
    __syncthreads();

    // each thread owns 8 consecutive positions
    int base = tid * 8;
    int c = 0;
    int lpos[8];
#pragma unroll
    for (int j = 0; j < 8; j++) {
        int l = base + j;
        if (l >= 1 && l <= LL - 2) {
            float sv = sh_s[l];
            if (sv < sh_s[l - 1] && sv < sh_s[l + 1]) lpos[c++] = l;
        }
    }

    sh_cnt[tid] = c;
    __syncthreads();
    for (int o = 1; o < 256; o <<= 1) {
        int v = (tid >= o) ? sh_cnt[tid - o] : 0;
        __syncthreads();
        sh_cnt[tid] += v;
        __syncthreads();
    }
    int excl  = sh_cnt[tid] - c;
    int total = sh_cnt[255];   // number of valleys in this row

    for (int i = 0; i < c; i++) {
        g_starts[b * MAXSEG + 1 + excl + i] = lpos[i];
        g_ends  [b * MAXSEG + excl + i]     = lpos[i] + 2;
    }
    if (tid == 0) {
        g_starts[b * MAXSEG + 0]   = 0;
        g_ends  [b * MAXSEG + total] = LL;      // min(L-1+2, L)
        g_counts[b] = total + 1;
    }

    // output_lengths = trunc((len_b / len_0) * M), written as float
    if (b == 0 && tid < BB) {
        float f = ((float)input_lengths[tid] / (float)input_lengths[0]) * (float)M;
        len_out[tid] = (float)(int)f;
    }
}

// ============================================================
// Kernel 3: per-segment weighted mean. grid = (M, B), 256 threads (d = tid)
// ============================================================
__global__ void k_reduce(const float* __restrict__ x,
                         float* __restrict__ out, int M) {
    int b = blockIdx.y;
    int m = blockIdx.x;
    int d = threadIdx.x;

    float res = 0.f;
    if (m < g_counts[b]) {
        int st = g_starts[b * MAXSEG + m];
        int en = g_ends  [b * MAXSEG + m];
        const float* xb = x + (size_t)b * LL * DD;
        const float* sb = g_s + b * LL;
        float num = 0.f, den = 0.f;
        for (int l = st; l < en; l++) {
            float sv = __ldg(&sb[l]);            // broadcast across warp
            den += sv;
            num += sv * __ldg(&xb[(size_t)l * DD + d]);
        }
        res = num / fmaxf(den, 1e-6f);
    }
    out[((size_t)b * M + m) * DD + d] = res;
}

// ============================================================
extern "C" void kernel_launch(void* const* d_in, const int* in_sizes, int n_in,
                              void* d_out, int out_size) {
    const float* x    = (const float*)d_in[0];
    const float* W    = (const float*)d_in[1];
    const float* bias = (const float*)d_in[2];
    const int*   il   = (const int*)d_in[3];
    float* out = (float*)d_out;

    // Derive M from out_size. Preferred layout: [B*M*D | B lengths | B*L s]
    const long long aux_full = (long long)BB + (long long)BB * LL;  // 16 + 32768
    long long rem = (long long)out_size - aux_full;
    int M;
    float *len_out, *s_out;

    if (rem > 0 && rem % (BB * DD) == 0) {
        M = (int)(rem / (BB * DD));
        len_out = out + (size_t)BB * M * DD;
        s_out   = len_out + BB;
    } else if (out_size % (BB * DD) == 0) {
        // output only
        M = out_size / (BB * DD);
        float* dl; float* ds;
        cudaGetSymbolAddress((void**)&dl, g_dummy_len);
        cudaGetSymbolAddress((void**)&ds, g_dummy_s);
        len_out = dl; s_out = ds;
    } else {
        // output + lengths
        M = (out_size - BB) / (BB * DD);
        len_out = out + (size_t)BB * M * DD;
        float* ds;
        cudaGetSymbolAddress((void**)&ds, g_dummy_s);
        s_out = ds;
    }
    if (M < 1) M = 1;

    // Stage 1: scores (one warp per row; 8 warps/block)
    int nwarps  = BB * LL;
    int nblocks = (nwarps * 32 + 255) / 256;
    k_score<<<nblocks, 256>>>(x, W, bias, s_out);

    // Stage 2: segment extraction (one block per batch row)
    k_segments<<<BB, 256>>>(il, len_out, M);

    // Stage 3: per-segment weighted mean
    dim3 grid3(M, BB);
    k_reduce<<<grid3, 256>>>(x, out, M);
}